// round 5
// baseline (speedup 1.0000x reference)
#include <cuda_runtime.h>
#include <math.h>

#define B   32
#define T   2048
#define H   1024
#define OUT 256

#define CHUNK  16                 // t-rows per block in main pass (fine grain)
#define NCHUNK (T / CHUNK)        // 128 chunks
#define GRP    8                  // rows per group in main pass
#define NGRP   (CHUNK / GRP)      // 2 groups
#define HC     16                 // h-chunks for ht partial (64 each)

// ---- scratch (__device__ globals; no allocation allowed) ----
__device__ float d_htp[HC * B * H];                   // h_t partials
__device__ float d_ht [B * H];                        // h_t
__device__ float d_v  [B * H];                        // v[b] = W1 @ h_t[b]
__device__ float d_scr[(size_t)B * NCHUNK * H];       // per-chunk context partials (16MB)
__device__ float d_md [(size_t)B * NCHUNK * 2];       // per-chunk (m, d)
__device__ float d_ctx[B * H];                        // context vector
__device__ int   d_cnt[32];                           // per-kt arrival counters (zero-init)

// ================= h_t: partial + last-block reduce (fused)
// grid (32 k-tiles, HC h-chunks), 256 threads
__global__ void __launch_bounds__(256) ht_kernel(const float* __restrict__ hs,
                                                 const float* __restrict__ W1,
                                                 const float* __restrict__ b1) {
    int kt = blockIdx.x, hc = blockIdx.y;
    int tid = threadIdx.x;
    int kl = tid & 31, bg = tid >> 5;
    __shared__ float hsl[B][64];
    int h0 = hc * 64;
    for (int i = tid; i < B * 64; i += 256) {
        int b = i >> 6, hh = i & 63;
        hsl[b][hh] = hs[((size_t)b * T + (T - 1)) * H + h0 + hh];
    }
    __syncthreads();
    int k = kt * 32 + kl;
    int b0 = bg * 4;
    float a0 = 0.f, a1 = 0.f, a2 = 0.f, a3 = 0.f;
    const float* w1p = W1 + (size_t)h0 * H + k;
#pragma unroll 16
    for (int hh = 0; hh < 64; hh++) {
        float w = w1p[(size_t)hh * H];
        a0 = fmaf(hsl[b0 + 0][hh], w, a0);
        a1 = fmaf(hsl[b0 + 1][hh], w, a1);
        a2 = fmaf(hsl[b0 + 2][hh], w, a2);
        a3 = fmaf(hsl[b0 + 3][hh], w, a3);
    }
    d_htp[((size_t)hc * B + b0 + 0) * H + k] = a0;
    d_htp[((size_t)hc * B + b0 + 1) * H + k] = a1;
    d_htp[((size_t)hc * B + b0 + 2) * H + k] = a2;
    d_htp[((size_t)hc * B + b0 + 3) * H + k] = a3;

    // last-arriving block for this kt does the reduce (+ bias)
    __threadfence();
    __syncthreads();
    __shared__ int amLast;
    if (tid == 0) amLast = (atomicAdd(&d_cnt[kt], 1) == HC - 1);
    __syncthreads();
    if (amLast) {
#pragma unroll
        for (int i = 0; i < 4; i++) {
            int b = (tid >> 5) * 4 + i;
            float a = b1[k];
#pragma unroll
            for (int c = 0; c < HC; c++) a += d_htp[((size_t)c * B + b) * H + k];
            d_ht[(size_t)b * H + k] = a;
        }
        if (tid == 0) d_cnt[kt] = 0;   // reset for next graph replay
    }
}

// ================= v[b,h] = dot(W1 row h, h_t[b])
__global__ void __launch_bounds__(256) v_kernel(const float* __restrict__ W1) {
    int ht8 = blockIdx.x, bg = blockIdx.y;
    int tid = threadIdx.x;
    int w = tid >> 5, lane = tid & 31;
    __shared__ float hts[4][H];
    for (int i = tid; i < 4 * H; i += 256) {
        int bi = i >> 10, k = i & (H - 1);
        hts[bi][k] = d_ht[(size_t)(bg * 4 + bi) * H + k];
    }
    __syncthreads();
    int h = ht8 * 8 + w;
    const float4* row = (const float4*)(W1 + (size_t)h * H);
    float a0 = 0.f, a1 = 0.f, a2 = 0.f, a3 = 0.f;
#pragma unroll
    for (int ki = 0; ki < 8; ki++) {
        float4 wv = row[ki * 32 + lane];
        int kb = (ki * 32 + lane) * 4;
        float4 t0 = *(const float4*)&hts[0][kb];
        float4 t1 = *(const float4*)&hts[1][kb];
        float4 t2 = *(const float4*)&hts[2][kb];
        float4 t3 = *(const float4*)&hts[3][kb];
        a0 = fmaf(wv.x, t0.x, fmaf(wv.y, t0.y, fmaf(wv.z, t0.z, fmaf(wv.w, t0.w, a0))));
        a1 = fmaf(wv.x, t1.x, fmaf(wv.y, t1.y, fmaf(wv.z, t1.z, fmaf(wv.w, t1.w, a1))));
        a2 = fmaf(wv.x, t2.x, fmaf(wv.y, t2.y, fmaf(wv.z, t2.z, fmaf(wv.w, t2.w, a2))));
        a3 = fmaf(wv.x, t3.x, fmaf(wv.y, t3.y, fmaf(wv.z, t3.z, fmaf(wv.w, t3.w, a3))));
    }
#pragma unroll
    for (int off = 16; off; off >>= 1) {
        a0 += __shfl_xor_sync(0xffffffffu, a0, off);
        a1 += __shfl_xor_sync(0xffffffffu, a1, off);
        a2 += __shfl_xor_sync(0xffffffffu, a2, off);
        a3 += __shfl_xor_sync(0xffffffffu, a3, off);
    }
    if (lane == 0) {
        d_v[(size_t)(bg * 4 + 0) * H + h] = a0;
        d_v[(size_t)(bg * 4 + 1) * H + h] = a1;
        d_v[(size_t)(bg * 4 + 2) * H + h] = a2;
        d_v[(size_t)(bg * 4 + 3) * H + h] = a3;
    }
}

// ================= main streaming pass: fine-grain chunks (16 rows/block)
// grid (NCHUNK, B), 256 threads, forced 4 CTAs/SM.
__global__ void __launch_bounds__(256, 4) main_pass_kernel(const float* __restrict__ hs) {
    int chunk = blockIdx.x;
    int b = blockIdx.y;
    int tid = threadIdx.x;
    int w = tid >> 5, lane = tid & 31;

    __shared__ float part[2][GRP][8];

    float4 vr = ((const float4*)(d_v + (size_t)b * H))[tid];
    float4 sa = make_float4(0.f, 0.f, 0.f, 0.f);
    float m = -INFINITY, d = 0.f;

    const float4* base = (const float4*)(hs + ((size_t)b * T + (size_t)chunk * CHUNK) * H) + tid;

#pragma unroll
    for (int g = 0; g < NGRP; g++) {
        float4 val[GRP];
#pragma unroll
        for (int j = 0; j < GRP; j++)
            val[j] = __ldcs(base + (size_t)(g * GRP + j) * (H / 4));

        float p[GRP];
#pragma unroll
        for (int j = 0; j < GRP; j++)
            p[j] = fmaf(val[j].x, vr.x, fmaf(val[j].y, vr.y,
                   fmaf(val[j].z, vr.z, val[j].w * vr.w)));

#pragma unroll
        for (int off = 16; off; off >>= 1) {
#pragma unroll
            for (int j = 0; j < GRP; j++)
                p[j] += __shfl_xor_sync(0xffffffffu, p[j], off);
        }
        if (lane == 0) {
#pragma unroll
            for (int j = 0; j < GRP; j++) part[g & 1][j][w] = p[j];
        }
        __syncthreads();

        float dt[GRP];
#pragma unroll
        for (int j = 0; j < GRP; j++) {
            float4 x = *(const float4*)&part[g & 1][j][0];
            float4 y = *(const float4*)&part[g & 1][j][4];
            dt[j] = ((x.x + x.y) + (x.z + x.w)) + ((y.x + y.y) + (y.z + y.w));
        }
#pragma unroll
        for (int j = 0; j < GRP; j++) {
            float mn = fmaxf(m, dt[j]);
            float sc = __expf(m - mn);      // 0 on first row (m=-inf)
            float wt = __expf(dt[j] - mn);
            d = d * sc + wt;
            sa.x = fmaf(sa.x, sc, wt * val[j].x);
            sa.y = fmaf(sa.y, sc, wt * val[j].y);
            sa.z = fmaf(sa.z, sc, wt * val[j].z);
            sa.w = fmaf(sa.w, sc, wt * val[j].w);
            m = mn;
        }
    }

    ((float4*)(d_scr + (size_t)(b * NCHUNK + chunk) * H))[tid] = sa;
    if (tid == 0) {
        d_md[(size_t)(b * NCHUNK + chunk) * 2 + 0] = m;
        d_md[(size_t)(b * NCHUNK + chunk) * 2 + 1] = d;
    }
}

// ================= grid combine: ctx[b,h] = sum_c w_c * s_c[h] / D
// grid (B, 4 quarters of 256 h), 256 threads
__global__ void __launch_bounds__(256) combine_kernel() {
    int b = blockIdx.x, q = blockIdx.y;
    int tid = threadIdx.x;
    __shared__ float mb[NCHUNK], db[NCHUNK], wc[NCHUNK];
    {
        float2 md = ((const float2*)d_md)[b * NCHUNK + tid];      // tid < 256 == NCHUNK*2/2
        mb[tid % NCHUNK] = 0.f;                                   // placeholder; overwritten below
    }
    // load (m,d) pairs: 128 chunks
    if (tid < NCHUNK) {
        mb[tid] = d_md[(size_t)(b * NCHUNK + tid) * 2 + 0];
        db[tid] = d_md[(size_t)(b * NCHUNK + tid) * 2 + 1];
    }
    __syncthreads();
    float M = mb[0];
#pragma unroll 16
    for (int c = 1; c < NCHUNK; c++) M = fmaxf(M, mb[c]);
    if (tid < NCHUNK) wc[tid] = __expf(mb[tid] - M);
    __syncthreads();
    float D = 0.f;
#pragma unroll 16
    for (int c = 0; c < NCHUNK; c++) D += wc[c] * db[c];
    float inv = 1.f / D;
    int h = q * 256 + tid;
    float a = 0.f;
#pragma unroll 8
    for (int c = 0; c < NCHUNK; c++)
        a = fmaf(wc[c], d_scr[(size_t)(b * NCHUNK + c) * H + h], a);
    d_ctx[(size_t)b * H + h] = a * inv;
}

// ================= final GEMM + tanh: grid (B, 8 o-tiles of 32), 256 threads
__global__ void __launch_bounds__(256) final_kernel(const float* __restrict__ Wv,
                                                    const float* __restrict__ bv,
                                                    float* __restrict__ out) {
    int b = blockIdx.x, ot = blockIdx.y;
    int tid = threadIdx.x;

    __shared__ float pre[2 * H];
    __shared__ float red[8][32];

    ((float4*)pre)[tid]       = ((const float4*)(d_ctx + (size_t)b * H))[tid];
    ((float4*)(pre + H))[tid] = ((const float4*)(d_ht  + (size_t)b * H))[tid];
    __syncthreads();

    int o = ot * 32 + (tid & 31);
    int jg = tid >> 5;
    const float* wp = Wv + (size_t)(jg * 256) * OUT + o;
    const float* pp = pre + jg * 256;
    float acc = 0.f;
#pragma unroll 8
    for (int jj = 0; jj < 256; jj++)
        acc = fmaf(pp[jj], wp[(size_t)jj * OUT], acc);
    red[jg][tid & 31] = acc;
    __syncthreads();

    if (tid < 32) {
        float a = bv[ot * 32 + tid];
#pragma unroll
        for (int k = 0; k < 8; k++) a += red[k][tid];
        out[(size_t)b * OUT + ot * 32 + tid] = tanhf(a);
    }
}

extern "C" void kernel_launch(void* const* d_in, const int* in_sizes, int n_in,
                              void* d_out, int out_size) {
    const float* hs = (const float*)d_in[0];
    const float* W1 = (const float*)d_in[1];
    const float* b1 = (const float*)d_in[2];
    const float* Wv = (const float*)d_in[3];
    const float* bv = (const float*)d_in[4];
    float* out = (float*)d_out;

    ht_kernel<<<dim3(32, HC), 256>>>(hs, W1, b1);
    v_kernel<<<dim3(128, 8), 256>>>(W1);
    main_pass_kernel<<<dim3(NCHUNK, B), 256>>>(hs);
    combine_kernel<<<dim3(B, 4), 256>>>();
    final_kernel<<<dim3(B, 8), 256>>>(Wv, bv, out);
}

// round 6
// speedup vs baseline: 1.3685x; 1.3685x over previous
#include <cuda_runtime.h>
#include <math.h>

#define B   32
#define T   2048
#define H   1024
#define OUT 256

#define GRP    8                  // rows per group in main pass
#define NGRPS  (T / GRP)          // 256 groups per batch
#define NP     12                 // persistent CTAs per batch (12*32=384 = single wave)
#define HC     16                 // h-chunks for ht partial (64 each)

// ---- scratch (__device__ globals; no allocation allowed) ----
__device__ float d_htp[HC * B * H];                   // h_t partials
__device__ float d_ht [B * H];                        // h_t
__device__ float d_v  [B * H];                        // v[b] = W1 @ h_t[b]
__device__ float d_scr[(size_t)B * NP * H];           // per-CTA context partials (1.5MB)
__device__ float d_md [(size_t)B * NP * 2];           // per-CTA (m, d)
__device__ int   d_cnt[32];                           // per-kt arrival counters (zero-init)

// ================= h_t: partial + last-block reduce (fused)
// grid (32 k-tiles, HC h-chunks), 256 threads
__global__ void __launch_bounds__(256) ht_kernel(const float* __restrict__ hs,
                                                 const float* __restrict__ W1,
                                                 const float* __restrict__ b1) {
    int kt = blockIdx.x, hc = blockIdx.y;
    int tid = threadIdx.x;
    int kl = tid & 31, bg = tid >> 5;
    __shared__ float hsl[B][64];
    int h0 = hc * 64;
    for (int i = tid; i < B * 64; i += 256) {
        int b = i >> 6, hh = i & 63;
        hsl[b][hh] = hs[((size_t)b * T + (T - 1)) * H + h0 + hh];
    }
    __syncthreads();
    int k = kt * 32 + kl;
    int b0 = bg * 4;
    float a0 = 0.f, a1 = 0.f, a2 = 0.f, a3 = 0.f;
    const float* w1p = W1 + (size_t)h0 * H + k;
#pragma unroll 16
    for (int hh = 0; hh < 64; hh++) {
        float w = w1p[(size_t)hh * H];
        a0 = fmaf(hsl[b0 + 0][hh], w, a0);
        a1 = fmaf(hsl[b0 + 1][hh], w, a1);
        a2 = fmaf(hsl[b0 + 2][hh], w, a2);
        a3 = fmaf(hsl[b0 + 3][hh], w, a3);
    }
    d_htp[((size_t)hc * B + b0 + 0) * H + k] = a0;
    d_htp[((size_t)hc * B + b0 + 1) * H + k] = a1;
    d_htp[((size_t)hc * B + b0 + 2) * H + k] = a2;
    d_htp[((size_t)hc * B + b0 + 3) * H + k] = a3;

    // last-arriving block for this kt does the reduce (+ bias)
    __threadfence();
    __syncthreads();
    __shared__ int amLast;
    if (tid == 0) amLast = (atomicAdd(&d_cnt[kt], 1) == HC - 1);
    __syncthreads();
    if (amLast) {
#pragma unroll
        for (int i = 0; i < 4; i++) {
            int b = (tid >> 5) * 4 + i;
            float a = b1[k];
#pragma unroll
            for (int c = 0; c < HC; c++) a += d_htp[((size_t)c * B + b) * H + k];
            d_ht[(size_t)b * H + k] = a;
        }
        if (tid == 0) d_cnt[kt] = 0;   // reset for next graph replay
    }
}

// ================= v[b,h] = dot(W1 row h, h_t[b])
__global__ void __launch_bounds__(256) v_kernel(const float* __restrict__ W1) {
    int ht8 = blockIdx.x, bg = blockIdx.y;
    int tid = threadIdx.x;
    int w = tid >> 5, lane = tid & 31;
    __shared__ float hts[4][H];
    for (int i = tid; i < 4 * H; i += 256) {
        int bi = i >> 10, k = i & (H - 1);
        hts[bi][k] = d_ht[(size_t)(bg * 4 + bi) * H + k];
    }
    __syncthreads();
    int h = ht8 * 8 + w;
    const float4* row = (const float4*)(W1 + (size_t)h * H);
    float a0 = 0.f, a1 = 0.f, a2 = 0.f, a3 = 0.f;
#pragma unroll
    for (int ki = 0; ki < 8; ki++) {
        float4 wv = row[ki * 32 + lane];
        int kb = (ki * 32 + lane) * 4;
        float4 t0 = *(const float4*)&hts[0][kb];
        float4 t1 = *(const float4*)&hts[1][kb];
        float4 t2 = *(const float4*)&hts[2][kb];
        float4 t3 = *(const float4*)&hts[3][kb];
        a0 = fmaf(wv.x, t0.x, fmaf(wv.y, t0.y, fmaf(wv.z, t0.z, fmaf(wv.w, t0.w, a0))));
        a1 = fmaf(wv.x, t1.x, fmaf(wv.y, t1.y, fmaf(wv.z, t1.z, fmaf(wv.w, t1.w, a1))));
        a2 = fmaf(wv.x, t2.x, fmaf(wv.y, t2.y, fmaf(wv.z, t2.z, fmaf(wv.w, t2.w, a2))));
        a3 = fmaf(wv.x, t3.x, fmaf(wv.y, t3.y, fmaf(wv.z, t3.z, fmaf(wv.w, t3.w, a3))));
    }
#pragma unroll
    for (int off = 16; off; off >>= 1) {
        a0 += __shfl_xor_sync(0xffffffffu, a0, off);
        a1 += __shfl_xor_sync(0xffffffffu, a1, off);
        a2 += __shfl_xor_sync(0xffffffffu, a2, off);
        a3 += __shfl_xor_sync(0xffffffffu, a3, off);
    }
    if (lane == 0) {
        d_v[(size_t)(bg * 4 + 0) * H + h] = a0;
        d_v[(size_t)(bg * 4 + 1) * H + h] = a1;
        d_v[(size_t)(bg * 4 + 2) * H + h] = a2;
        d_v[(size_t)(bg * 4 + 3) * H + h] = a3;
    }
}

// ================= main streaming pass: persistent single wave
// grid (NP, B) = 384 CTAs (one wave at 3 CTAs/SM). CTA p handles groups
// [p*NGRPS/NP, (p+1)*NGRPS/NP) of batch b with ONE online accumulator.
__global__ void __launch_bounds__(256) main_pass_kernel(const float* __restrict__ hs) {
    int p = blockIdx.x;
    int b = blockIdx.y;
    int tid = threadIdx.x;
    int w = tid >> 5, lane = tid & 31;

    __shared__ float part[2][GRP][8];

    float4 vr = ((const float4*)(d_v + (size_t)b * H))[tid];
    float4 sa = make_float4(0.f, 0.f, 0.f, 0.f);
    float m = -INFINITY, d = 0.f;

    int g0 = (p * NGRPS) / NP;
    int g1 = ((p + 1) * NGRPS) / NP;

    const float4* base = (const float4*)(hs + (size_t)b * T * H) + tid;

    for (int g = g0; g < g1; g++) {
        float4 val[GRP];
#pragma unroll
        for (int j = 0; j < GRP; j++)
            val[j] = __ldcs(base + (size_t)(g * GRP + j) * (H / 4));

        float pd[GRP];
#pragma unroll
        for (int j = 0; j < GRP; j++)
            pd[j] = fmaf(val[j].x, vr.x, fmaf(val[j].y, vr.y,
                    fmaf(val[j].z, vr.z, val[j].w * vr.w)));

#pragma unroll
        for (int off = 16; off; off >>= 1) {
#pragma unroll
            for (int j = 0; j < GRP; j++)
                pd[j] += __shfl_xor_sync(0xffffffffu, pd[j], off);
        }
        if (lane == 0) {
#pragma unroll
            for (int j = 0; j < GRP; j++) part[g & 1][j][w] = pd[j];
        }
        __syncthreads();

        float dt[GRP];
#pragma unroll
        for (int j = 0; j < GRP; j++) {
            float4 x = *(const float4*)&part[g & 1][j][0];
            float4 y = *(const float4*)&part[g & 1][j][4];
            dt[j] = ((x.x + x.y) + (x.z + x.w)) + ((y.x + y.y) + (y.z + y.w));
        }
#pragma unroll
        for (int j = 0; j < GRP; j++) {
            float mn = fmaxf(m, dt[j]);
            float sc = __expf(m - mn);      // 0 on first row (m=-inf)
            float wt = __expf(dt[j] - mn);
            d = d * sc + wt;
            sa.x = fmaf(sa.x, sc, wt * val[j].x);
            sa.y = fmaf(sa.y, sc, wt * val[j].y);
            sa.z = fmaf(sa.z, sc, wt * val[j].z);
            sa.w = fmaf(sa.w, sc, wt * val[j].w);
            m = mn;
        }
    }

    ((float4*)(d_scr + (size_t)(b * NP + p) * H))[tid] = sa;
    if (tid == 0) {
        d_md[(size_t)(b * NP + p) * 2 + 0] = m;
        d_md[(size_t)(b * NP + p) * 2 + 1] = d;
    }
}

// ================= fused combine + final GEMM + tanh
// grid (B, 8 o-tiles of 32), 256 threads. d_scr is tiny (1.5MB) so the
// 8x ot re-read costs ~12MB of L2-resident traffic.
__global__ void __launch_bounds__(256) combine_final_kernel(const float* __restrict__ Wv,
                                                            const float* __restrict__ bv,
                                                            float* __restrict__ out) {
    int b = blockIdx.x, ot = blockIdx.y;
    int tid = threadIdx.x;

    __shared__ float pre[2 * H];
    __shared__ float wcs[NP];
    __shared__ float mdsh[2 * NP];
    __shared__ float red[8][32];

    if (tid < 2 * NP) mdsh[tid] = d_md[(size_t)b * NP * 2 + tid];
    __syncthreads();

    float M = mdsh[0];
#pragma unroll
    for (int c = 1; c < NP; c++) M = fmaxf(M, mdsh[2 * c]);
    if (tid < NP) wcs[tid] = __expf(mdsh[2 * tid] - M);
    __syncthreads();
    float D = 0.f;
#pragma unroll
    for (int c = 0; c < NP; c++) D += wcs[c] * mdsh[2 * c + 1];
    float inv = 1.f / D;

#pragma unroll
    for (int q = 0; q < 4; q++) {
        int h = q * 256 + tid;
        float a = 0.f;
#pragma unroll
        for (int c = 0; c < NP; c++)
            a = fmaf(wcs[c], d_scr[(size_t)(b * NP + c) * H + h], a);
        pre[h] = a * inv;
    }
    ((float4*)(pre + H))[tid] = ((const float4*)(d_ht + (size_t)b * H))[tid];
    __syncthreads();

    int o = ot * 32 + (tid & 31);
    int jg = tid >> 5;
    const float* wp = Wv + (size_t)(jg * 256) * OUT + o;
    const float* pp = pre + jg * 256;
    float acc = 0.f;
#pragma unroll 8
    for (int jj = 0; jj < 256; jj++)
        acc = fmaf(pp[jj], wp[(size_t)jj * OUT], acc);
    red[jg][tid & 31] = acc;
    __syncthreads();

    if (tid < 32) {
        float a = bv[ot * 32 + tid];
#pragma unroll
        for (int k = 0; k < 8; k++) a += red[k][tid];
        out[(size_t)b * OUT + ot * 32 + tid] = tanhf(a);
    }
}

extern "C" void kernel_launch(void* const* d_in, const int* in_sizes, int n_in,
                              void* d_out, int out_size) {
    const float* hs = (const float*)d_in[0];
    const float* W1 = (const float*)d_in[1];
    const float* b1 = (const float*)d_in[2];
    const float* Wv = (const float*)d_in[3];
    const float* bv = (const float*)d_in[4];
    float* out = (float*)d_out;

    ht_kernel<<<dim3(32, HC), 256>>>(hs, W1, b1);
    v_kernel<<<dim3(128, 8), 256>>>(W1);
    main_pass_kernel<<<dim3(NP, B), 256>>>(hs);
    combine_final_kernel<<<dim3(B, 8), 256>>>(Wv, bv, out);
}